// round 5
// baseline (speedup 1.0000x reference)
#include <cuda_runtime.h>
#include <math.h>

#define Nn 100000
#define Ee 1600000
#define Ff 256
#define Hh 64

// ---- device scratch (static: no allocation allowed) ----
// g_cnt starts zero (static init) and is re-zeroed by cleanup_kernel at the
// end of every kernel_launch, so hist can run first.
__device__ float g_h[(size_t)Nn * Hh];   // node features (layer input)
__device__ float g_q[(size_t)Nn * Hh];
__device__ float g_k[(size_t)Nn * Hh];
__device__ float g_v[(size_t)Nn * Hh];
__device__ float g_e[(size_t)Ee];        // per-edge alpha, then exp(alpha-m)
__device__ int   g_cnt[Nn];              // per-dst degree (zeroed at end of run)
__device__ int   g_off[Nn];              // CSR exclusive offsets
__device__ int   g_cur[Nn];              // fill cursors
__device__ int   g_csrc[Ee];             // CSR: source node per slot
__device__ int   g_ceid[Ee];             // CSR: original edge id per slot

__device__ __forceinline__ float gelu_exact(float v) {
    return 0.5f * v * (1.0f + erff(v * 0.70710678118654752440f));
}

__device__ __forceinline__ unsigned f2tf32(float v) {
    unsigned r;
    asm("cvt.rna.tf32.f32 %0, %1;" : "=r"(r) : "f"(v));
    return r;
}

__device__ __forceinline__ void mma_tf32(float& c0, float& c1, float& c2, float& c3,
                                         unsigned a0, unsigned a1, unsigned a2, unsigned a3,
                                         unsigned b0, unsigned b1) {
    asm volatile(
        "mma.sync.aligned.m16n8k8.row.col.f32.tf32.tf32.f32 "
        "{%0,%1,%2,%3},{%4,%5,%6,%7},{%8,%9},{%0,%1,%2,%3};"
        : "+f"(c0), "+f"(c1), "+f"(c2), "+f"(c3)
        : "r"(a0), "r"(a1), "r"(a2), "r"(a3), "r"(b0), "r"(b1));
}

// ============================================================
// CSR build
// ============================================================
__global__ void hist_kernel(const int* __restrict__ dst) {
    int i = blockIdx.x * blockDim.x + threadIdx.x;
    if (i < Ee) atomicAdd(&g_cnt[__ldg(dst + i)], 1);
}

// single-block scan: 1024 threads, contiguous chunk per thread
__global__ void scan_kernel() {
    __shared__ int ssum[1024];
    const int C = (Nn + 1023) / 1024;   // 98
    int t = threadIdx.x;
    int lo = t * C, hi = min(lo + C, Nn);
    int s = 0;
    for (int i = lo; i < hi; i++) s += g_cnt[i];
    ssum[t] = s;
    __syncthreads();
#pragma unroll
    for (int o = 1; o < 1024; o <<= 1) {
        int add = (t >= o) ? ssum[t - o] : 0;
        __syncthreads();
        ssum[t] += add;
        __syncthreads();
    }
    int run = ssum[t] - s;   // exclusive prefix of this thread's chunk
    for (int i = lo; i < hi; i++) {
        int c = g_cnt[i];
        g_off[i] = run;
        g_cur[i] = run;
        run += c;
    }
}

__global__ void fill_kernel(const int* __restrict__ src,
                            const int* __restrict__ dst) {
    int i = blockIdx.x * blockDim.x + threadIdx.x;
    if (i >= Ee) return;
    int d = __ldg(dst + i);
    int pos = atomicAdd(&g_cur[d], 1);
    g_csrc[pos] = __ldg(src + i);
    g_ceid[pos] = i;
}

__global__ void cleanup_kernel() {
    int i = blockIdx.x * blockDim.x + threadIdx.x;
    if (i < Nn) g_cnt[i] = 0;
}

// ============================================================
// proj (tensor core): g_h = gelu(x @ W_proj + b)  [100000,256]x[256,64]
// ============================================================
#define PROJ_SMEM_U ((128 * 36 + 64 * 260) * 4)
__global__ void proj_mma_kernel(const float* __restrict__ x,
                                const float* __restrict__ W,
                                const float* __restrict__ b) {
    extern __shared__ unsigned sm[];
    unsigned* As = sm;             // 128*36
    unsigned* Bs = sm + 128 * 36;  // 64*260
    int tid = threadIdx.x;
    int w = tid >> 5, lane = tid & 31;
    int g = lane >> 2, c = lane & 3;
    size_t row0 = (size_t)blockIdx.x * 128;

    for (int i = tid; i < 256 * 64; i += 256) {
        int k = i >> 6, n = i & 63;
        Bs[n * 260 + k] = f2tf32(W[i]);
    }

    float acc[8][4];
#pragma unroll
    for (int nt = 0; nt < 8; nt++)
#pragma unroll
        for (int e = 0; e < 4; e++) acc[nt][e] = 0.0f;

    const float4* x4 = (const float4*)x;
    for (int k0 = 0; k0 < 256; k0 += 32) {
        __syncthreads();
#pragma unroll
        for (int j = 0; j < 4; j++) {
            int f = tid + 256 * j;
            int r = f >> 3, c8 = f & 7;
            size_t rr = row0 + r; if (rr >= Nn) rr = Nn - 1;
            float4 v = x4[rr * 64 + (k0 >> 2) + c8];
            unsigned* p = As + r * 36 + c8 * 4;
            p[0] = f2tf32(v.x); p[1] = f2tf32(v.y);
            p[2] = f2tf32(v.z); p[3] = f2tf32(v.w);
        }
        __syncthreads();

#pragma unroll
        for (int ks = 0; ks < 4; ks++) {
            int kk = ks * 8;
            const unsigned* ap = As + (w * 16 + g) * 36 + kk + c;
            unsigned a0 = ap[0], a1 = ap[8 * 36], a2 = ap[4], a3 = ap[8 * 36 + 4];
#pragma unroll
            for (int nt = 0; nt < 8; nt++) {
                const unsigned* bp = Bs + (nt * 8 + g) * 260 + k0 + kk + c;
                mma_tf32(acc[nt][0], acc[nt][1], acc[nt][2], acc[nt][3],
                         a0, a1, a2, a3, bp[0], bp[4]);
            }
        }
    }

    size_t r0 = row0 + w * 16 + g;
    size_t r1 = r0 + 8;
#pragma unroll
    for (int nt = 0; nt < 8; nt++) {
        int col = nt * 8 + c * 2;
        float b0 = __ldg(b + col), b1 = __ldg(b + col + 1);
        if (r0 < Nn) {
            g_h[r0 * 64 + col]     = gelu_exact(acc[nt][0] + b0);
            g_h[r0 * 64 + col + 1] = gelu_exact(acc[nt][1] + b1);
        }
        if (r1 < Nn) {
            g_h[r1 * 64 + col]     = gelu_exact(acc[nt][2] + b0);
            g_h[r1 * 64 + col + 1] = gelu_exact(acc[nt][3] + b1);
        }
    }
}

// ============================================================
// qkv (tensor core): g_q/g_k/g_v = g_h @ {Wq,Wk,Wv}  [100000,64]x[64,192]
// ============================================================
#define QKV_SMEM_U ((128 * 68 + 192 * 68) * 4)
__global__ void qkv_mma_kernel(const float* __restrict__ Wq,
                               const float* __restrict__ Wk,
                               const float* __restrict__ Wv) {
    extern __shared__ unsigned sm[];
    unsigned* As = sm;             // 128*68
    unsigned* Bs = sm + 128 * 68;  // 192*68
    int tid = threadIdx.x;
    int w = tid >> 5, lane = tid & 31;
    int g = lane >> 2, c = lane & 3;
    size_t row0 = (size_t)blockIdx.x * 128;

    for (int i = tid; i < 64 * 64; i += 256) {
        int k = i >> 6, n = i & 63;
        Bs[n * 68 + k]         = f2tf32(Wq[i]);
        Bs[(64 + n) * 68 + k]  = f2tf32(Wk[i]);
        Bs[(128 + n) * 68 + k] = f2tf32(Wv[i]);
    }
    const float4* h4 = (const float4*)g_h;
#pragma unroll
    for (int j = 0; j < 8; j++) {
        int f = tid + 256 * j;
        int r = f >> 4, c16 = f & 15;
        size_t rr = row0 + r; if (rr >= Nn) rr = Nn - 1;
        float4 v = h4[rr * 16 + c16];
        unsigned* p = As + r * 68 + c16 * 4;
        p[0] = f2tf32(v.x); p[1] = f2tf32(v.y);
        p[2] = f2tf32(v.z); p[3] = f2tf32(v.w);
    }
    __syncthreads();

    float acc[24][4];
#pragma unroll
    for (int nt = 0; nt < 24; nt++)
#pragma unroll
        for (int e = 0; e < 4; e++) acc[nt][e] = 0.0f;

#pragma unroll
    for (int ks = 0; ks < 8; ks++) {
        int kk = ks * 8;
        const unsigned* ap = As + (w * 16 + g) * 68 + kk + c;
        unsigned a0 = ap[0], a1 = ap[8 * 68], a2 = ap[4], a3 = ap[8 * 68 + 4];
#pragma unroll
        for (int nt = 0; nt < 24; nt++) {
            const unsigned* bp = Bs + (nt * 8 + g) * 68 + kk + c;
            mma_tf32(acc[nt][0], acc[nt][1], acc[nt][2], acc[nt][3],
                     a0, a1, a2, a3, bp[0], bp[4]);
        }
    }

    size_t r0 = row0 + w * 16 + g;
    size_t r1 = r0 + 8;
#pragma unroll
    for (int nt = 0; nt < 24; nt++) {
        int col = nt * 8 + c * 2;
        float* outp = (col < 64) ? g_q : (col < 128) ? g_k : g_v;
        int cc = col & 63;
        if (r0 < Nn) {
            outp[r0 * 64 + cc]     = acc[nt][0];
            outp[r0 * 64 + cc + 1] = acc[nt][1];
        }
        if (r1 < Nn) {
            outp[r1 * 64 + cc]     = acc[nt][2];
            outp[r1 * 64 + cc + 1] = acc[nt][3];
        }
    }
}

// ============================================================
// fused GAT layer: warp per destination node, half-warp per edge,
// float4 per lane (16 lanes x 4 dims = 64).
// ============================================================
template <int LAYER>
__global__ void gat_kernel(const float* __restrict__ Wsig,
                           const float* __restrict__ bsig,
                           float* __restrict__ attn_out,
                           float* __restrict__ signals) {
    int w = (blockIdx.x * blockDim.x + threadIdx.x) >> 5;
    int lane = threadIdx.x & 31;
    if (w >= Nn) return;
    int hw = lane >> 4;          // half-warp id 0/1
    int lj = lane & 15;          // lane within half-warp
    int start = g_off[w];
    int deg = g_cnt[w];

    float4 q4 = ((const float4*)(g_q))[(size_t)w * 16 + lj];

    // ---- phase 1: scores + max (2 edges per iteration) ----
    float m = 0.0f;
    for (int i = 0; i < deg; i += 2) {
        int idx = i + hw;
        bool active = (idx < deg);
        int slot = start + (active ? idx : i);
        int s = g_csrc[slot];
        float4 k4 = ((const float4*)(g_k))[(size_t)s * 16 + lj];
        float p = q4.x * k4.x + q4.y * k4.y + q4.z * k4.z + q4.w * k4.w;
#pragma unroll
        for (int o = 8; o; o >>= 1) p += __shfl_xor_sync(0xFFFFFFFFu, p, o);
        float a = fmaxf(p * 0.125f, 0.0f);
        if (active) {
            if (lj == 0) g_e[start + idx] = a;
            m = fmaxf(m, a);
        }
    }
    m = fmaxf(m, __shfl_xor_sync(0xFFFFFFFFu, m, 16));
    __syncwarp();

    // ---- phase 2: exp + denom (edge-parallel over 32 lanes) ----
    float sum = 0.0f;
    for (int i = lane; i < deg; i += 32) {
        float e = expf(g_e[start + i] - m);
        g_e[start + i] = e;
        sum += e;
    }
#pragma unroll
    for (int o = 16; o; o >>= 1) sum += __shfl_xor_sync(0xFFFFFFFFu, sum, o);
    float inv = 1.0f / (sum + 1e-16f);
    __syncwarp();

    // ---- phase 3: weighted gather of v (2 edges per iteration) ----
    float4 acc = make_float4(0.f, 0.f, 0.f, 0.f);
    for (int i = 0; i < deg; i += 2) {
        int idx = i + hw;
        bool active = (idx < deg);
        int slot = start + (active ? idx : i);
        int s = g_csrc[slot];
        float a = g_e[slot] * inv;
        if (active) {
            if (lj == 0) attn_out[g_ceid[start + idx]] = a;
            float4 v4 = ((const float4*)(g_v))[(size_t)s * 16 + lj];
            acc.x += a * v4.x; acc.y += a * v4.y;
            acc.z += a * v4.z; acc.w += a * v4.w;
        }
    }

    if (LAYER == 0) {
        // combine halves, lanes 0-15 write float4
        acc.x += __shfl_xor_sync(0xFFFFFFFFu, acc.x, 16);
        acc.y += __shfl_xor_sync(0xFFFFFFFFu, acc.y, 16);
        acc.z += __shfl_xor_sync(0xFFFFFFFFu, acc.z, 16);
        acc.w += __shfl_xor_sync(0xFFFFFFFFu, acc.w, 16);
        if (hw == 0) {
            float4 o4;
            o4.x = gelu_exact(acc.x); o4.y = gelu_exact(acc.y);
            o4.z = gelu_exact(acc.z); o4.w = gelu_exact(acc.w);
            ((float4*)(g_h))[(size_t)w * 16 + lj] = o4;
        }
    } else {
        // signal: reduce acc . Wsig over all 32 lanes (halves sum implicitly)
        float4 ws = __ldg(((const float4*)Wsig) + lj);
        float p = acc.x * ws.x + acc.y * ws.y + acc.z * ws.z + acc.w * ws.w;
#pragma unroll
        for (int o = 16; o; o >>= 1) p += __shfl_xor_sync(0xFFFFFFFFu, p, o);
        if (lane == 0) signals[w] = p + __ldg(bsig);
    }
}

// ============================================================
// host launcher
// launch order puts proj_mma at index 3 (the ncu-profiled slot).
// ============================================================
extern "C" void kernel_launch(void* const* d_in, const int* in_sizes, int n_in,
                              void* d_out, int out_size) {
    const float* x    = (const float*)d_in[0];
    const int*   ei   = (const int*)d_in[1];
    const int*   src  = ei;          // edge_index[0]
    const int*   dst  = ei + Ee;     // edge_index[1]
    const float* Wp   = (const float*)d_in[2];
    const float* bp   = (const float*)d_in[3];
    const float* Wq1  = (const float*)d_in[4];
    const float* Wk1  = (const float*)d_in[5];
    const float* Wv1  = (const float*)d_in[6];
    const float* Wq2  = (const float*)d_in[7];
    const float* Wk2  = (const float*)d_in[8];
    const float* Wv2  = (const float*)d_in[9];
    const float* Wsig = (const float*)d_in[10];
    const float* bsig = (const float*)d_in[11];

    float* out     = (float*)d_out;
    float* signals = out;            // [Nn]
    float* attn1   = out + Nn;       // [Ee]
    float* attn2   = out + Nn + Ee;  // [Ee]

    cudaFuncSetAttribute(proj_mma_kernel, cudaFuncAttributeMaxDynamicSharedMemorySize, PROJ_SMEM_U);
    cudaFuncSetAttribute(qkv_mma_kernel,  cudaFuncAttributeMaxDynamicSharedMemorySize, QKV_SMEM_U);

    const int nblk = (Nn + 127) / 128;   // 782

    // ---- CSR build (g_cnt is zero on entry; re-zeroed by cleanup at end) ----
    hist_kernel<<<(Ee + 255) / 256, 256>>>(dst);                 // 0
    scan_kernel<<<1, 1024>>>();                                  // 1
    fill_kernel<<<(Ee + 255) / 256, 256>>>(src, dst);            // 2

    // ---- proj + gelu (profiled slot: index 3) ----
    proj_mma_kernel<<<nblk, 256, PROJ_SMEM_U>>>(x, Wp, bp);      // 3

    // ---- layer 1 ----
    qkv_mma_kernel<<<nblk, 256, QKV_SMEM_U>>>(Wq1, Wk1, Wv1);    // 4
    gat_kernel<0><<<(Nn + 7) / 8, 256>>>(Wsig, bsig, attn1, signals);  // 5

    // ---- layer 2 ----
    qkv_mma_kernel<<<nblk, 256, QKV_SMEM_U>>>(Wq2, Wk2, Wv2);    // 6
    gat_kernel<1><<<(Nn + 7) / 8, 256>>>(Wsig, bsig, attn2, signals);  // 7

    // ---- reset g_cnt for next replay ----
    cleanup_kernel<<<(Nn + 255) / 256, 256>>>();                 // 8
}

// round 6
// speedup vs baseline: 1.2992x; 1.2992x over previous
#include <cuda_runtime.h>
#include <math.h>

#define Nn 100000
#define Ee 1600000
#define Ff 256
#define Hh 64
#define NB_SCAN 98   // ceil(Nn/1024)

// ---- device scratch (static: no allocation allowed) ----
// g_cnt starts zero (static init) and is re-zeroed by cleanup_kernel at the
// end of every kernel_launch, so hist can run first.
__device__ float g_h[(size_t)Nn * Hh];   // node features (layer input)
__device__ float g_q[(size_t)Nn * Hh];
__device__ float g_k[(size_t)Nn * Hh];
__device__ float g_v[(size_t)Nn * Hh];
__device__ float g_e[(size_t)Ee];        // per-edge alpha, then exp(alpha-m)
__device__ int   g_cnt[Nn];              // per-dst degree (zeroed at end of run)
__device__ int   g_off[Nn];              // CSR exclusive offsets
__device__ int   g_cur[Nn];              // fill cursors
__device__ int   g_csrc[Ee];             // CSR: source node per slot
__device__ int   g_ceid[Ee];             // CSR: original edge id per slot
__device__ int   g_bsum[128];
__device__ int   g_bpre[128];

__device__ __forceinline__ float gelu_exact(float v) {
    return 0.5f * v * (1.0f + erff(v * 0.70710678118654752440f));
}

__device__ __forceinline__ unsigned f2tf32(float v) {
    unsigned r;
    asm("cvt.rna.tf32.f32 %0, %1;" : "=r"(r) : "f"(v));
    return r;
}

__device__ __forceinline__ void mma_tf32(float& c0, float& c1, float& c2, float& c3,
                                         unsigned a0, unsigned a1, unsigned a2, unsigned a3,
                                         unsigned b0, unsigned b1) {
    asm volatile(
        "mma.sync.aligned.m16n8k8.row.col.f32.tf32.tf32.f32 "
        "{%0,%1,%2,%3},{%4,%5,%6,%7},{%8,%9},{%0,%1,%2,%3};"
        : "+f"(c0), "+f"(c1), "+f"(c2), "+f"(c3)
        : "r"(a0), "r"(a1), "r"(a2), "r"(a3), "r"(b0), "r"(b1));
}

// ============================================================
// CSR build
// ============================================================
__global__ void hist_kernel(const int* __restrict__ dst) {
    int i = blockIdx.x * blockDim.x + threadIdx.x;
    if (i < Ee) atomicAdd(&g_cnt[__ldg(dst + i)], 1);
}

__global__ void scanA_kernel() {
    __shared__ int wsum[32];
    int i = blockIdx.x * 1024 + threadIdx.x;
    int lane = threadIdx.x & 31, wid = threadIdx.x >> 5;
    int v = (i < Nn) ? g_cnt[i] : 0;
    int x = v;
#pragma unroll
    for (int o = 1; o < 32; o <<= 1) {
        int t = __shfl_up_sync(0xFFFFFFFFu, x, o);
        if (lane >= o) x += t;
    }
    if (lane == 31) wsum[wid] = x;
    __syncthreads();
    if (wid == 0) {
        int y = wsum[lane];
#pragma unroll
        for (int o = 1; o < 32; o <<= 1) {
            int t = __shfl_up_sync(0xFFFFFFFFu, y, o);
            if (lane >= o) y += t;
        }
        wsum[lane] = y;
    }
    __syncthreads();
    int excl = x - v + (wid ? wsum[wid - 1] : 0);
    if (i < Nn) g_off[i] = excl;
    if (threadIdx.x == 1023) g_bsum[blockIdx.x] = excl + v;
}

__global__ void scanB_kernel() {
    __shared__ int sm[128];
    int t = threadIdx.x;
    int v = (t < NB_SCAN) ? g_bsum[t] : 0;
    sm[t] = v;
    __syncthreads();
#pragma unroll
    for (int o = 1; o < 128; o <<= 1) {
        int add = (t >= o) ? sm[t - o] : 0;
        __syncthreads();
        sm[t] += add;
        __syncthreads();
    }
    if (t < NB_SCAN) g_bpre[t] = sm[t] - v;  // exclusive
}

__global__ void scanC_kernel() {
    int i = blockIdx.x * 1024 + threadIdx.x;
    if (i < Nn) {
        int o = g_off[i] + g_bpre[blockIdx.x];
        g_off[i] = o;
        g_cur[i] = o;
    }
}

__global__ void fill_kernel(const int* __restrict__ src,
                            const int* __restrict__ dst) {
    int i = blockIdx.x * blockDim.x + threadIdx.x;
    if (i >= Ee) return;
    int d = __ldg(dst + i);
    int pos = atomicAdd(&g_cur[d], 1);
    g_csrc[pos] = __ldg(src + i);
    g_ceid[pos] = i;
}

__global__ void cleanup_kernel() {
    int i = blockIdx.x * blockDim.x + threadIdx.x;
    if (i < Nn) g_cnt[i] = 0;
}

// ============================================================
// proj (tensor core): g_h = gelu(x @ W_proj + b)  [100000,256]x[256,64]
// ============================================================
#define PROJ_SMEM_U ((128 * 36 + 64 * 260) * 4)
__global__ void proj_mma_kernel(const float* __restrict__ x,
                                const float* __restrict__ W,
                                const float* __restrict__ b) {
    extern __shared__ unsigned sm[];
    unsigned* As = sm;             // 128*36
    unsigned* Bs = sm + 128 * 36;  // 64*260
    int tid = threadIdx.x;
    int w = tid >> 5, lane = tid & 31;
    int g = lane >> 2, c = lane & 3;
    size_t row0 = (size_t)blockIdx.x * 128;

    for (int i = tid; i < 256 * 64; i += 256) {
        int k = i >> 6, n = i & 63;
        Bs[n * 260 + k] = f2tf32(W[i]);
    }

    float acc[8][4];
#pragma unroll
    for (int nt = 0; nt < 8; nt++)
#pragma unroll
        for (int e = 0; e < 4; e++) acc[nt][e] = 0.0f;

    const float4* x4 = (const float4*)x;
    for (int k0 = 0; k0 < 256; k0 += 32) {
        __syncthreads();
#pragma unroll
        for (int j = 0; j < 4; j++) {
            int f = tid + 256 * j;
            int r = f >> 3, c8 = f & 7;
            size_t rr = row0 + r; if (rr >= Nn) rr = Nn - 1;
            float4 v = x4[rr * 64 + (k0 >> 2) + c8];
            unsigned* p = As + r * 36 + c8 * 4;
            p[0] = f2tf32(v.x); p[1] = f2tf32(v.y);
            p[2] = f2tf32(v.z); p[3] = f2tf32(v.w);
        }
        __syncthreads();

#pragma unroll
        for (int ks = 0; ks < 4; ks++) {
            int kk = ks * 8;
            const unsigned* ap = As + (w * 16 + g) * 36 + kk + c;
            unsigned a0 = ap[0], a1 = ap[8 * 36], a2 = ap[4], a3 = ap[8 * 36 + 4];
#pragma unroll
            for (int nt = 0; nt < 8; nt++) {
                const unsigned* bp = Bs + (nt * 8 + g) * 260 + k0 + kk + c;
                mma_tf32(acc[nt][0], acc[nt][1], acc[nt][2], acc[nt][3],
                         a0, a1, a2, a3, bp[0], bp[4]);
            }
        }
    }

    size_t r0 = row0 + w * 16 + g;
    size_t r1 = r0 + 8;
#pragma unroll
    for (int nt = 0; nt < 8; nt++) {
        int col = nt * 8 + c * 2;
        float b0 = __ldg(b + col), b1 = __ldg(b + col + 1);
        if (r0 < Nn) {
            g_h[r0 * 64 + col]     = gelu_exact(acc[nt][0] + b0);
            g_h[r0 * 64 + col + 1] = gelu_exact(acc[nt][1] + b1);
        }
        if (r1 < Nn) {
            g_h[r1 * 64 + col]     = gelu_exact(acc[nt][2] + b0);
            g_h[r1 * 64 + col + 1] = gelu_exact(acc[nt][3] + b1);
        }
    }
}

// ============================================================
// qkv (tensor core): g_q/g_k/g_v = g_h @ {Wq,Wk,Wv}  [100000,64]x[64,192]
// ============================================================
#define QKV_SMEM_U ((128 * 68 + 192 * 68) * 4)
__global__ void qkv_mma_kernel(const float* __restrict__ Wq,
                               const float* __restrict__ Wk,
                               const float* __restrict__ Wv) {
    extern __shared__ unsigned sm[];
    unsigned* As = sm;             // 128*68
    unsigned* Bs = sm + 128 * 68;  // 192*68
    int tid = threadIdx.x;
    int w = tid >> 5, lane = tid & 31;
    int g = lane >> 2, c = lane & 3;
    size_t row0 = (size_t)blockIdx.x * 128;

    for (int i = tid; i < 64 * 64; i += 256) {
        int k = i >> 6, n = i & 63;
        Bs[n * 68 + k]         = f2tf32(Wq[i]);
        Bs[(64 + n) * 68 + k]  = f2tf32(Wk[i]);
        Bs[(128 + n) * 68 + k] = f2tf32(Wv[i]);
    }
    const float4* h4 = (const float4*)g_h;
#pragma unroll
    for (int j = 0; j < 8; j++) {
        int f = tid + 256 * j;
        int r = f >> 4, c16 = f & 15;
        size_t rr = row0 + r; if (rr >= Nn) rr = Nn - 1;
        float4 v = h4[rr * 16 + c16];
        unsigned* p = As + r * 68 + c16 * 4;
        p[0] = f2tf32(v.x); p[1] = f2tf32(v.y);
        p[2] = f2tf32(v.z); p[3] = f2tf32(v.w);
    }
    __syncthreads();

    float acc[24][4];
#pragma unroll
    for (int nt = 0; nt < 24; nt++)
#pragma unroll
        for (int e = 0; e < 4; e++) acc[nt][e] = 0.0f;

#pragma unroll
    for (int ks = 0; ks < 8; ks++) {
        int kk = ks * 8;
        const unsigned* ap = As + (w * 16 + g) * 68 + kk + c;
        unsigned a0 = ap[0], a1 = ap[8 * 68], a2 = ap[4], a3 = ap[8 * 68 + 4];
#pragma unroll
        for (int nt = 0; nt < 24; nt++) {
            const unsigned* bp = Bs + (nt * 8 + g) * 68 + kk + c;
            mma_tf32(acc[nt][0], acc[nt][1], acc[nt][2], acc[nt][3],
                     a0, a1, a2, a3, bp[0], bp[4]);
        }
    }

    size_t r0 = row0 + w * 16 + g;
    size_t r1 = r0 + 8;
#pragma unroll
    for (int nt = 0; nt < 24; nt++) {
        int col = nt * 8 + c * 2;
        float* outp = (col < 64) ? g_q : (col < 128) ? g_k : g_v;
        int cc = col & 63;
        if (r0 < Nn) {
            outp[r0 * 64 + cc]     = acc[nt][0];
            outp[r0 * 64 + cc + 1] = acc[nt][1];
        }
        if (r1 < Nn) {
            outp[r1 * 64 + cc]     = acc[nt][2];
            outp[r1 * 64 + cc + 1] = acc[nt][3];
        }
    }
}

// ============================================================
// fused GAT layer: warp per destination node, half-warp per edge,
// float4 per lane (16 lanes x 4 dims = 64).
// ============================================================
template <int LAYER>
__global__ void gat_kernel(const float* __restrict__ Wsig,
                           const float* __restrict__ bsig,
                           float* __restrict__ attn_out,
                           float* __restrict__ signals) {
    int w = (blockIdx.x * blockDim.x + threadIdx.x) >> 5;
    int lane = threadIdx.x & 31;
    if (w >= Nn) return;
    int hw = lane >> 4;          // half-warp id 0/1
    int lj = lane & 15;          // lane within half-warp
    int start = g_off[w];
    int deg = g_cnt[w];

    float4 q4 = ((const float4*)(g_q))[(size_t)w * 16 + lj];

    // ---- phase 1: scores + max (2 edges per iteration) ----
    float m = 0.0f;
    for (int i = 0; i < deg; i += 2) {
        int idx = i + hw;
        bool active = (idx < deg);
        int slot = start + (active ? idx : i);
        int s = g_csrc[slot];
        float4 k4 = ((const float4*)(g_k))[(size_t)s * 16 + lj];
        float p = q4.x * k4.x + q4.y * k4.y + q4.z * k4.z + q4.w * k4.w;
#pragma unroll
        for (int o = 8; o; o >>= 1) p += __shfl_xor_sync(0xFFFFFFFFu, p, o);
        float a = fmaxf(p * 0.125f, 0.0f);
        if (active) {
            if (lj == 0) g_e[start + idx] = a;
            m = fmaxf(m, a);
        }
    }
    m = fmaxf(m, __shfl_xor_sync(0xFFFFFFFFu, m, 16));
    __syncwarp();

    // ---- phase 2: exp + denom (edge-parallel over 32 lanes) ----
    float sum = 0.0f;
    for (int i = lane; i < deg; i += 32) {
        float e = expf(g_e[start + i] - m);
        g_e[start + i] = e;
        sum += e;
    }
#pragma unroll
    for (int o = 16; o; o >>= 1) sum += __shfl_xor_sync(0xFFFFFFFFu, sum, o);
    float inv = 1.0f / (sum + 1e-16f);
    __syncwarp();

    // ---- phase 3: weighted gather of v (2 edges per iteration) ----
    float4 acc = make_float4(0.f, 0.f, 0.f, 0.f);
    for (int i = 0; i < deg; i += 2) {
        int idx = i + hw;
        bool active = (idx < deg);
        int slot = start + (active ? idx : i);
        int s = g_csrc[slot];
        float a = g_e[slot] * inv;
        if (active) {
            if (lj == 0) attn_out[g_ceid[start + idx]] = a;
            float4 v4 = ((const float4*)(g_v))[(size_t)s * 16 + lj];
            acc.x += a * v4.x; acc.y += a * v4.y;
            acc.z += a * v4.z; acc.w += a * v4.w;
        }
    }

    if (LAYER == 0) {
        acc.x += __shfl_xor_sync(0xFFFFFFFFu, acc.x, 16);
        acc.y += __shfl_xor_sync(0xFFFFFFFFu, acc.y, 16);
        acc.z += __shfl_xor_sync(0xFFFFFFFFu, acc.z, 16);
        acc.w += __shfl_xor_sync(0xFFFFFFFFu, acc.w, 16);
        if (hw == 0) {
            float4 o4;
            o4.x = gelu_exact(acc.x); o4.y = gelu_exact(acc.y);
            o4.z = gelu_exact(acc.z); o4.w = gelu_exact(acc.w);
            ((float4*)(g_h))[(size_t)w * 16 + lj] = o4;
        }
    } else {
        float4 ws = __ldg(((const float4*)Wsig) + lj);
        float p = acc.x * ws.x + acc.y * ws.y + acc.z * ws.z + acc.w * ws.w;
#pragma unroll
        for (int o = 16; o; o >>= 1) p += __shfl_xor_sync(0xFFFFFFFFu, p, o);
        if (lane == 0) signals[w] = p + __ldg(bsig);
    }
}

// ============================================================
// host launcher — qkv_mma at launch index 3 (the ncu-profiled slot).
// ============================================================
extern "C" void kernel_launch(void* const* d_in, const int* in_sizes, int n_in,
                              void* d_out, int out_size) {
    const float* x    = (const float*)d_in[0];
    const int*   ei   = (const int*)d_in[1];
    const int*   src  = ei;          // edge_index[0]
    const int*   dst  = ei + Ee;     // edge_index[1]
    const float* Wp   = (const float*)d_in[2];
    const float* bp   = (const float*)d_in[3];
    const float* Wq1  = (const float*)d_in[4];
    const float* Wk1  = (const float*)d_in[5];
    const float* Wv1  = (const float*)d_in[6];
    const float* Wq2  = (const float*)d_in[7];
    const float* Wk2  = (const float*)d_in[8];
    const float* Wv2  = (const float*)d_in[9];
    const float* Wsig = (const float*)d_in[10];
    const float* bsig = (const float*)d_in[11];

    float* out     = (float*)d_out;
    float* signals = out;            // [Nn]
    float* attn1   = out + Nn;       // [Ee]
    float* attn2   = out + Nn + Ee;  // [Ee]

    cudaFuncSetAttribute(proj_mma_kernel, cudaFuncAttributeMaxDynamicSharedMemorySize, PROJ_SMEM_U);
    cudaFuncSetAttribute(qkv_mma_kernel,  cudaFuncAttributeMaxDynamicSharedMemorySize, QKV_SMEM_U);

    const int nblk = (Nn + 127) / 128;   // 782

    proj_mma_kernel<<<nblk, 256, PROJ_SMEM_U>>>(x, Wp, bp);           // 0
    hist_kernel<<<(Ee + 255) / 256, 256>>>(dst);                      // 1
    scanA_kernel<<<NB_SCAN, 1024>>>();                                // 2
    qkv_mma_kernel<<<nblk, 256, QKV_SMEM_U>>>(Wq1, Wk1, Wv1);         // 3 (profiled)
    scanB_kernel<<<1, 128>>>();                                       // 4
    scanC_kernel<<<NB_SCAN, 1024>>>();                                // 5
    fill_kernel<<<(Ee + 255) / 256, 256>>>(src, dst);                 // 6
    gat_kernel<0><<<(Nn + 7) / 8, 256>>>(Wsig, bsig, attn1, signals); // 7
    qkv_mma_kernel<<<nblk, 256, QKV_SMEM_U>>>(Wq2, Wk2, Wv2);         // 8
    gat_kernel<1><<<(Nn + 7) / 8, 256>>>(Wsig, bsig, attn2, signals); // 9
    cleanup_kernel<<<(Nn + 255) / 256, 256>>>();                      // 10
}

// round 7
// speedup vs baseline: 1.3808x; 1.0628x over previous
#include <cuda_runtime.h>
#include <math.h>

#define Nn 100000
#define Ee 1600000
#define Ff 256
#define Hh 64
#define NB_SCAN 98   // ceil(Nn/1024)

// ---- device scratch (static: no allocation allowed) ----
// g_cnt starts zero (static init) and is re-zeroed by cleanup_kernel at the
// end of every kernel_launch, so hist can run first.
__device__ float g_h[(size_t)Nn * Hh];   // node features (layer input)
__device__ float g_q[(size_t)Nn * Hh];
__device__ float g_k[(size_t)Nn * Hh];
__device__ float g_v[(size_t)Nn * Hh];
__device__ float g_e[(size_t)Ee];        // per-edge alpha, then exp(alpha-m)
__device__ int   g_cnt[Nn];              // per-dst degree (zeroed at end of run)
__device__ int   g_off[Nn];              // CSR exclusive offsets
__device__ int   g_cur[Nn];              // fill cursors
__device__ int   g_csrc[Ee];             // CSR: source node per slot
__device__ int   g_ceid[Ee];             // CSR: original edge id per slot
__device__ int   g_bsum[128];
__device__ int   g_bpre[128];

__device__ __forceinline__ float gelu_exact(float v) {
    return 0.5f * v * (1.0f + erff(v * 0.70710678118654752440f));
}

__device__ __forceinline__ unsigned f2tf32(float v) {
    unsigned r;
    asm("cvt.rna.tf32.f32 %0, %1;" : "=r"(r) : "f"(v));
    return r;
}

__device__ __forceinline__ void mma_tf32(float& c0, float& c1, float& c2, float& c3,
                                         unsigned a0, unsigned a1, unsigned a2, unsigned a3,
                                         unsigned b0, unsigned b1) {
    asm volatile(
        "mma.sync.aligned.m16n8k8.row.col.f32.tf32.tf32.f32 "
        "{%0,%1,%2,%3},{%4,%5,%6,%7},{%8,%9},{%0,%1,%2,%3};"
        : "+f"(c0), "+f"(c1), "+f"(c2), "+f"(c3)
        : "r"(a0), "r"(a1), "r"(a2), "r"(a3), "r"(b0), "r"(b1));
}

// ============================================================
// CSR build
// ============================================================
__global__ void hist_kernel(const int* __restrict__ dst) {
    int i = blockIdx.x * blockDim.x + threadIdx.x;
    if (i < Ee) atomicAdd(&g_cnt[__ldg(dst + i)], 1);
}

__global__ void scanA_kernel() {
    __shared__ int wsum[32];
    int i = blockIdx.x * 1024 + threadIdx.x;
    int lane = threadIdx.x & 31, wid = threadIdx.x >> 5;
    int v = (i < Nn) ? g_cnt[i] : 0;
    int x = v;
#pragma unroll
    for (int o = 1; o < 32; o <<= 1) {
        int t = __shfl_up_sync(0xFFFFFFFFu, x, o);
        if (lane >= o) x += t;
    }
    if (lane == 31) wsum[wid] = x;
    __syncthreads();
    if (wid == 0) {
        int y = wsum[lane];
#pragma unroll
        for (int o = 1; o < 32; o <<= 1) {
            int t = __shfl_up_sync(0xFFFFFFFFu, y, o);
            if (lane >= o) y += t;
        }
        wsum[lane] = y;
    }
    __syncthreads();
    int excl = x - v + (wid ? wsum[wid - 1] : 0);
    if (i < Nn) g_off[i] = excl;
    if (threadIdx.x == 1023) g_bsum[blockIdx.x] = excl + v;
}

__global__ void scanB_kernel() {
    __shared__ int sm[128];
    int t = threadIdx.x;
    int v = (t < NB_SCAN) ? g_bsum[t] : 0;
    sm[t] = v;
    __syncthreads();
#pragma unroll
    for (int o = 1; o < 128; o <<= 1) {
        int add = (t >= o) ? sm[t - o] : 0;
        __syncthreads();
        sm[t] += add;
        __syncthreads();
    }
    if (t < NB_SCAN) g_bpre[t] = sm[t] - v;  // exclusive
}

__global__ void scanC_kernel() {
    int i = blockIdx.x * 1024 + threadIdx.x;
    if (i < Nn) {
        int o = g_off[i] + g_bpre[blockIdx.x];
        g_off[i] = o;
        g_cur[i] = o;
    }
}

__global__ void fill_kernel(const int* __restrict__ src,
                            const int* __restrict__ dst) {
    int i = blockIdx.x * blockDim.x + threadIdx.x;
    if (i >= Ee) return;
    int d = __ldg(dst + i);
    int pos = atomicAdd(&g_cur[d], 1);
    g_csrc[pos] = __ldg(src + i);
    g_ceid[pos] = i;
}

__global__ void cleanup_kernel() {
    int i = blockIdx.x * blockDim.x + threadIdx.x;
    if (i < Nn) g_cnt[i] = 0;
}

// ============================================================
// proj (tensor core): g_h = gelu(x @ W_proj + b)  [100000,256]x[256,64]
// register-prefetch double buffering of the A (x) tile.
// ============================================================
#define PROJ_SMEM_U ((128 * 36 + 64 * 260) * 4)
__global__ void proj_mma_kernel(const float* __restrict__ x,
                                const float* __restrict__ W,
                                const float* __restrict__ b) {
    extern __shared__ unsigned sm[];
    unsigned* As = sm;             // 128*36
    unsigned* Bs = sm + 128 * 36;  // 64*260
    int tid = threadIdx.x;
    int w = tid >> 5, lane = tid & 31;
    int g = lane >> 2, c = lane & 3;
    size_t row0 = (size_t)blockIdx.x * 128;

    for (int i = tid; i < 256 * 64; i += 256) {
        int k = i >> 6, n = i & 63;
        Bs[n * 260 + k] = f2tf32(W[i]);
    }

    float acc[8][4];
#pragma unroll
    for (int nt = 0; nt < 8; nt++)
#pragma unroll
        for (int e = 0; e < 4; e++) acc[nt][e] = 0.0f;

    // per-thread staging coordinates (4 float4 slices per chunk)
    const float4* x4 = (const float4*)x;
    int rA[4], cA[4];
    size_t xbase[4];
#pragma unroll
    for (int j = 0; j < 4; j++) {
        int f = tid + 256 * j;
        rA[j] = f >> 3; cA[j] = f & 7;
        size_t rr = row0 + rA[j]; if (rr >= Nn) rr = Nn - 1;
        xbase[j] = rr * 64 + cA[j];
    }

    // preload chunk 0
    float4 pre[4];
#pragma unroll
    for (int j = 0; j < 4; j++) pre[j] = x4[xbase[j]];

    for (int k0 = 0; k0 < 256; k0 += 32) {
        __syncthreads();   // prev chunk's frag reads done
#pragma unroll
        for (int j = 0; j < 4; j++) {
            unsigned* p = As + rA[j] * 36 + cA[j] * 4;
            p[0] = f2tf32(pre[j].x); p[1] = f2tf32(pre[j].y);
            p[2] = f2tf32(pre[j].z); p[3] = f2tf32(pre[j].w);
        }
        __syncthreads();

        // prefetch next chunk (overlaps the MMA phase below)
        if (k0 + 32 < 256) {
            int kidx = (k0 + 32) >> 2;
#pragma unroll
            for (int j = 0; j < 4; j++) pre[j] = x4[xbase[j] + kidx];
        }

#pragma unroll
        for (int ks = 0; ks < 4; ks++) {
            int kk = ks * 8;
            const unsigned* ap = As + (w * 16 + g) * 36 + kk + c;
            unsigned a0 = ap[0], a1 = ap[8 * 36], a2 = ap[4], a3 = ap[8 * 36 + 4];
#pragma unroll
            for (int nt = 0; nt < 8; nt++) {
                const unsigned* bp = Bs + (nt * 8 + g) * 260 + k0 + kk + c;
                mma_tf32(acc[nt][0], acc[nt][1], acc[nt][2], acc[nt][3],
                         a0, a1, a2, a3, bp[0], bp[4]);
            }
        }
    }

    size_t r0 = row0 + w * 16 + g;
    size_t r1 = r0 + 8;
#pragma unroll
    for (int nt = 0; nt < 8; nt++) {
        int col = nt * 8 + c * 2;
        float b0 = __ldg(b + col), b1 = __ldg(b + col + 1);
        if (r0 < Nn) {
            g_h[r0 * 64 + col]     = gelu_exact(acc[nt][0] + b0);
            g_h[r0 * 64 + col + 1] = gelu_exact(acc[nt][1] + b1);
        }
        if (r1 < Nn) {
            g_h[r1 * 64 + col]     = gelu_exact(acc[nt][2] + b0);
            g_h[r1 * 64 + col + 1] = gelu_exact(acc[nt][3] + b1);
        }
    }
}

// ============================================================
// qkv (tensor core): g_q/g_k/g_v = g_h @ {Wq,Wk,Wv}  [100000,64]x[64,192]
// 512 threads / 16 warps; warp tile 16 rows x 96 cols (12 n-tiles, 48 accs)
// -> half the accumulator registers of the old version, 2x warps resident.
// ============================================================
#define QKV_SMEM_U ((128 * 68 + 192 * 68) * 4)
__global__ void __launch_bounds__(512)
qkv_mma_kernel(const float* __restrict__ Wq,
               const float* __restrict__ Wk,
               const float* __restrict__ Wv) {
    extern __shared__ unsigned sm[];
    unsigned* As = sm;             // 128*68
    unsigned* Bs = sm + 128 * 68;  // 192*68
    int tid = threadIdx.x;
    int wid = tid >> 5, lane = tid & 31;
    int g = lane >> 2, c = lane & 3;
    int mi = wid & 7;              // 16-row group 0..7
    int nj = wid >> 3;             // 96-col half 0/1
    size_t row0 = (size_t)blockIdx.x * 128;

    for (int i = tid; i < 64 * 64; i += 512) {
        int k = i >> 6, n = i & 63;
        Bs[n * 68 + k]         = f2tf32(Wq[i]);
        Bs[(64 + n) * 68 + k]  = f2tf32(Wk[i]);
        Bs[(128 + n) * 68 + k] = f2tf32(Wv[i]);
    }
    const float4* h4 = (const float4*)g_h;
#pragma unroll
    for (int j = 0; j < 4; j++) {
        int f = tid + 512 * j;           // 0..2047
        int r = f >> 4, c16 = f & 15;
        size_t rr = row0 + r; if (rr >= Nn) rr = Nn - 1;
        float4 v = h4[rr * 16 + c16];
        unsigned* p = As + r * 68 + c16 * 4;
        p[0] = f2tf32(v.x); p[1] = f2tf32(v.y);
        p[2] = f2tf32(v.z); p[3] = f2tf32(v.w);
    }
    __syncthreads();

    float acc[12][4];
#pragma unroll
    for (int nt = 0; nt < 12; nt++)
#pragma unroll
        for (int e = 0; e < 4; e++) acc[nt][e] = 0.0f;

#pragma unroll
    for (int ks = 0; ks < 8; ks++) {
        int kk = ks * 8;
        const unsigned* ap = As + (mi * 16 + g) * 68 + kk + c;
        unsigned a0 = ap[0], a1 = ap[8 * 68], a2 = ap[4], a3 = ap[8 * 68 + 4];
#pragma unroll
        for (int nt = 0; nt < 12; nt++) {
            const unsigned* bp = Bs + (nj * 96 + nt * 8 + g) * 68 + kk + c;
            mma_tf32(acc[nt][0], acc[nt][1], acc[nt][2], acc[nt][3],
                     a0, a1, a2, a3, bp[0], bp[4]);
        }
    }

    size_t r0 = row0 + mi * 16 + g;
    size_t r1 = r0 + 8;
#pragma unroll
    for (int nt = 0; nt < 12; nt++) {
        int col = nj * 96 + nt * 8 + c * 2;
        float* outp = (col < 64) ? g_q : (col < 128) ? g_k : g_v;
        int cc = col & 63;
        if (r0 < Nn) {
            outp[r0 * 64 + cc]     = acc[nt][0];
            outp[r0 * 64 + cc + 1] = acc[nt][1];
        }
        if (r1 < Nn) {
            outp[r1 * 64 + cc]     = acc[nt][2];
            outp[r1 * 64 + cc + 1] = acc[nt][3];
        }
    }
}

// ============================================================
// fused GAT layer: warp per destination node, half-warp per edge,
// float4 per lane; phases 1&3 unrolled x2 (4 edges in flight).
// ============================================================
template <int LAYER>
__global__ void gat_kernel(const float* __restrict__ Wsig,
                           const float* __restrict__ bsig,
                           float* __restrict__ attn_out,
                           float* __restrict__ signals) {
    int w = (blockIdx.x * blockDim.x + threadIdx.x) >> 5;
    int lane = threadIdx.x & 31;
    if (w >= Nn) return;
    int hw = lane >> 4;          // half-warp id 0/1
    int lj = lane & 15;          // lane within half-warp
    int start = g_off[w];
    int deg = g_cnt[w];

    float4 q4 = ((const float4*)(g_q))[(size_t)w * 16 + lj];

    // ---- phase 1: scores + max ----
    float m = 0.0f;
    int i = 0;
    for (; i + 4 <= deg; i += 4) {
        int iA = i + hw, iB = i + 2 + hw;
        int sA = g_csrc[start + iA];
        int sB = g_csrc[start + iB];
        float4 kA = ((const float4*)(g_k))[(size_t)sA * 16 + lj];
        float4 kB = ((const float4*)(g_k))[(size_t)sB * 16 + lj];
        float pA = q4.x * kA.x + q4.y * kA.y + q4.z * kA.z + q4.w * kA.w;
        float pB = q4.x * kB.x + q4.y * kB.y + q4.z * kB.z + q4.w * kB.w;
#pragma unroll
        for (int o = 8; o; o >>= 1) {
            pA += __shfl_xor_sync(0xFFFFFFFFu, pA, o);
            pB += __shfl_xor_sync(0xFFFFFFFFu, pB, o);
        }
        float aA = fmaxf(pA * 0.125f, 0.0f);
        float aB = fmaxf(pB * 0.125f, 0.0f);
        if (lj == 0) { g_e[start + iA] = aA; g_e[start + iB] = aB; }
        m = fmaxf(m, fmaxf(aA, aB));
    }
    for (; i < deg; i += 2) {
        int idx = i + hw;
        bool active = (idx < deg);
        int slot = start + (active ? idx : i);
        int s = g_csrc[slot];
        float4 k4 = ((const float4*)(g_k))[(size_t)s * 16 + lj];
        float p = q4.x * k4.x + q4.y * k4.y + q4.z * k4.z + q4.w * k4.w;
#pragma unroll
        for (int o = 8; o; o >>= 1) p += __shfl_xor_sync(0xFFFFFFFFu, p, o);
        float a = fmaxf(p * 0.125f, 0.0f);
        if (active) {
            if (lj == 0) g_e[start + idx] = a;
            m = fmaxf(m, a);
        }
    }
    m = fmaxf(m, __shfl_xor_sync(0xFFFFFFFFu, m, 16));
    __syncwarp();

    // ---- phase 2: exp + denom (edge-parallel over 32 lanes) ----
    float sum = 0.0f;
    for (int t = lane; t < deg; t += 32) {
        float e = expf(g_e[start + t] - m);
        g_e[start + t] = e;
        sum += e;
    }
#pragma unroll
    for (int o = 16; o; o >>= 1) sum += __shfl_xor_sync(0xFFFFFFFFu, sum, o);
    float inv = 1.0f / (sum + 1e-16f);
    __syncwarp();

    // ---- phase 3: weighted gather of v ----
    float4 acc = make_float4(0.f, 0.f, 0.f, 0.f);
    i = 0;
    for (; i + 4 <= deg; i += 4) {
        int iA = i + hw, iB = i + 2 + hw;
        int sA = g_csrc[start + iA];
        int sB = g_csrc[start + iB];
        float aA = g_e[start + iA] * inv;
        float aB = g_e[start + iB] * inv;
        float4 vA = ((const float4*)(g_v))[(size_t)sA * 16 + lj];
        float4 vB = ((const float4*)(g_v))[(size_t)sB * 16 + lj];
        if (lj == 0) {
            attn_out[g_ceid[start + iA]] = aA;
            attn_out[g_ceid[start + iB]] = aB;
        }
        acc.x += aA * vA.x + aB * vB.x;
        acc.y += aA * vA.y + aB * vB.y;
        acc.z += aA * vA.z + aB * vB.z;
        acc.w += aA * vA.w + aB * vB.w;
    }
    for (; i < deg; i += 2) {
        int idx = i + hw;
        bool active = (idx < deg);
        int slot = start + (active ? idx : i);
        int s = g_csrc[slot];
        float a = g_e[slot] * inv;
        if (active) {
            if (lj == 0) attn_out[g_ceid[start + idx]] = a;
            float4 v4 = ((const float4*)(g_v))[(size_t)s * 16 + lj];
            acc.x += a * v4.x; acc.y += a * v4.y;
            acc.z += a * v4.z; acc.w += a * v4.w;
        }
    }

    if (LAYER == 0) {
        acc.x += __shfl_xor_sync(0xFFFFFFFFu, acc.x, 16);
        acc.y += __shfl_xor_sync(0xFFFFFFFFu, acc.y, 16);
        acc.z += __shfl_xor_sync(0xFFFFFFFFu, acc.z, 16);
        acc.w += __shfl_xor_sync(0xFFFFFFFFu, acc.w, 16);
        if (hw == 0) {
            float4 o4;
            o4.x = gelu_exact(acc.x); o4.y = gelu_exact(acc.y);
            o4.z = gelu_exact(acc.z); o4.w = gelu_exact(acc.w);
            ((float4*)(g_h))[(size_t)w * 16 + lj] = o4;
        }
    } else {
        float4 ws = __ldg(((const float4*)Wsig) + lj);
        float p = acc.x * ws.x + acc.y * ws.y + acc.z * ws.z + acc.w * ws.w;
#pragma unroll
        for (int o = 16; o; o >>= 1) p += __shfl_xor_sync(0xFFFFFFFFu, p, o);
        if (lane == 0) signals[w] = p + __ldg(bsig);
    }
}

// ============================================================
// host launcher — qkv_mma at launch index 3 (the ncu-profiled slot).
// ============================================================
extern "C" void kernel_launch(void* const* d_in, const int* in_sizes, int n_in,
                              void* d_out, int out_size) {
    const float* x    = (const float*)d_in[0];
    const int*   ei   = (const int*)d_in[1];
    const int*   src  = ei;          // edge_index[0]
    const int*   dst  = ei + Ee;     // edge_index[1]
    const float* Wp   = (const float*)d_in[2];
    const float* bp   = (const float*)d_in[3];
    const float* Wq1  = (const float*)d_in[4];
    const float* Wk1  = (const float*)d_in[5];
    const float* Wv1  = (const float*)d_in[6];
    const float* Wq2  = (const float*)d_in[7];
    const float* Wk2  = (const float*)d_in[8];
    const float* Wv2  = (const float*)d_in[9];
    const float* Wsig = (const float*)d_in[10];
    const float* bsig = (const float*)d_in[11];

    float* out     = (float*)d_out;
    float* signals = out;            // [Nn]
    float* attn1   = out + Nn;       // [Ee]
    float* attn2   = out + Nn + Ee;  // [Ee]

    cudaFuncSetAttribute(proj_mma_kernel, cudaFuncAttributeMaxDynamicSharedMemorySize, PROJ_SMEM_U);
    cudaFuncSetAttribute(qkv_mma_kernel,  cudaFuncAttributeMaxDynamicSharedMemorySize, QKV_SMEM_U);

    const int nblk = (Nn + 127) / 128;   // 782

    proj_mma_kernel<<<nblk, 256, PROJ_SMEM_U>>>(x, Wp, bp);           // 0
    hist_kernel<<<(Ee + 255) / 256, 256>>>(dst);                      // 1
    scanA_kernel<<<NB_SCAN, 1024>>>();                                // 2
    qkv_mma_kernel<<<nblk, 512, QKV_SMEM_U>>>(Wq1, Wk1, Wv1);         // 3 (profiled)
    scanB_kernel<<<1, 128>>>();                                       // 4
    scanC_kernel<<<NB_SCAN, 1024>>>();                                // 5
    fill_kernel<<<(Ee + 255) / 256, 256>>>(src, dst);                 // 6
    gat_kernel<0><<<(Nn + 7) / 8, 256>>>(Wsig, bsig, attn1, signals); // 7
    qkv_mma_kernel<<<nblk, 512, QKV_SMEM_U>>>(Wq2, Wk2, Wv2);         // 8
    gat_kernel<1><<<(Nn + 7) / 8, 256>>>(Wsig, bsig, attn2, signals); // 9
    cleanup_kernel<<<(Nn + 255) / 256, 256>>>();                      // 10
}